// round 9
// baseline (speedup 1.0000x reference)
#include <cuda_runtime.h>

// ---------------------------------------------------------------------------
// GAT 3-layer forward, cross-layer pipelined on two streams.
// Row-split: first NH=5056 rows ("a"), rest ("b"). Schedule:
//   main: G0 | A0a | G1a | A1a | G2a | FINa
//   s2:   CSR |       A0b | G1b |  A1b | G2b | FINb
// with A*b staggered after A*a so agg (mem-bound) overlaps GEMM (FMA-bound).
// H and as/ad are ping-ponged by layer parity to avoid cross-layer hazards.
// ---------------------------------------------------------------------------

#define MAXN 10240
#define MAXE 340000

__device__ float g_H[2][MAXN * 256];
__device__ float g_X[MAXN * 256];
__device__ float g_as[2][MAXN * 4];
__device__ float g_ad[2][MAXN * 4];
__device__ int   g_cnt[MAXN];
__device__ int   g_off[MAXN + 1];
__device__ int   g_wp[MAXN];
__device__ int   g_csr_src[MAXE];

// ---------------------------------------------------------------------------
// GEMM: C = A@B. 64x64 block tile, 128 threads, 8x4/thread, BK=16, register
// prefetch, fused attention-dot epilogue. rowOff selects the row range.
// ---------------------------------------------------------------------------
__global__ void __launch_bounds__(128) gemm64att(
    const float* __restrict__ A, const float* __restrict__ B,
    float* __restrict__ C,
    const float* __restrict__ asw, const float* __restrict__ adw,
    float* __restrict__ as_o, float* __restrict__ ad_o,
    int M, int N, int K, int heads, int rowOff)
{
    __shared__ float As[16][68];
    __shared__ float Bs[16][68];
    int tid = threadIdx.x;
    int tx = tid & 15, ty = tid >> 4;
    int row0 = rowOff + blockIdx.x * 64, col0 = blockIdx.y * 64;

    int ar0 = tid >> 2,          akq0 = (tid & 3) * 4;
    int ar1 = (tid + 128) >> 2,  akq1 = ((tid + 128) & 3) * 4;
    int bk0 = tid >> 4,          bcq0 = (tid & 15) * 4;
    int bk1 = (tid + 128) >> 4,  bcq1 = bcq0;

    float4 ap0, ap1, bp0, bp1;
    {
        int g0 = row0 + ar0, g1 = row0 + ar1;
        ap0 = (g0 < M) ? *reinterpret_cast<const float4*>(A + (size_t)g0 * K + akq0)
                       : make_float4(0.f, 0.f, 0.f, 0.f);
        ap1 = (g1 < M) ? *reinterpret_cast<const float4*>(A + (size_t)g1 * K + akq1)
                       : make_float4(0.f, 0.f, 0.f, 0.f);
        bp0 = *reinterpret_cast<const float4*>(B + (size_t)bk0 * N + col0 + bcq0);
        bp1 = *reinterpret_cast<const float4*>(B + (size_t)bk1 * N + col0 + bcq1);
    }

    float acc[8][4] = {};

    for (int k0 = 0; k0 < K; k0 += 16) {
        As[akq0 + 0][ar0] = ap0.x; As[akq0 + 1][ar0] = ap0.y;
        As[akq0 + 2][ar0] = ap0.z; As[akq0 + 3][ar0] = ap0.w;
        As[akq1 + 0][ar1] = ap1.x; As[akq1 + 1][ar1] = ap1.y;
        As[akq1 + 2][ar1] = ap1.z; As[akq1 + 3][ar1] = ap1.w;
        *reinterpret_cast<float4*>(&Bs[bk0][bcq0]) = bp0;
        *reinterpret_cast<float4*>(&Bs[bk1][bcq1]) = bp1;
        __syncthreads();

        if (k0 + 16 < K) {
            int g0 = row0 + ar0, g1 = row0 + ar1;
            int kn = k0 + 16;
            ap0 = (g0 < M) ? *reinterpret_cast<const float4*>(A + (size_t)g0 * K + kn + akq0)
                           : make_float4(0.f, 0.f, 0.f, 0.f);
            ap1 = (g1 < M) ? *reinterpret_cast<const float4*>(A + (size_t)g1 * K + kn + akq1)
                           : make_float4(0.f, 0.f, 0.f, 0.f);
            bp0 = *reinterpret_cast<const float4*>(B + (size_t)(kn + bk0) * N + col0 + bcq0);
            bp1 = *reinterpret_cast<const float4*>(B + (size_t)(kn + bk1) * N + col0 + bcq1);
        }

        #pragma unroll
        for (int kk = 0; kk < 16; kk++) {
            float4 a0 = *reinterpret_cast<const float4*>(&As[kk][ty * 8]);
            float4 a1 = *reinterpret_cast<const float4*>(&As[kk][ty * 8 + 4]);
            float4 b4 = *reinterpret_cast<const float4*>(&Bs[kk][tx * 4]);
            float av[8] = {a0.x, a0.y, a0.z, a0.w, a1.x, a1.y, a1.z, a1.w};
            float bv[4] = {b4.x, b4.y, b4.z, b4.w};
            #pragma unroll
            for (int i = 0; i < 8; i++)
                #pragma unroll
                for (int j = 0; j < 4; j++)
                    acc[i][j] += av[i] * bv[j];
        }
        __syncthreads();
    }

    #pragma unroll
    for (int i = 0; i < 8; i++) {
        int gr = row0 + ty * 8 + i;
        if (gr < M) {
            float4 v = make_float4(acc[i][0], acc[i][1], acc[i][2], acc[i][3]);
            *reinterpret_cast<float4*>(C + (size_t)gr * N + col0 + tx * 4) = v;
        }
    }

    float asv[4], adv_[4];
    #pragma unroll
    for (int j = 0; j < 4; j++) {
        asv[j]  = asw[col0 + tx * 4 + j];
        adv_[j] = adw[col0 + tx * 4 + j];
    }
    int h = blockIdx.y;
    #pragma unroll
    for (int i = 0; i < 8; i++) {
        float ss = 0.f, sd = 0.f;
        #pragma unroll
        for (int j = 0; j < 4; j++) {
            ss += acc[i][j] * asv[j];
            sd += acc[i][j] * adv_[j];
        }
        #pragma unroll
        for (int o = 1; o <= 8; o <<= 1) {
            ss += __shfl_xor_sync(0xffffffffu, ss, o);
            sd += __shfl_xor_sync(0xffffffffu, sd, o);
        }
        if (tx == 0) {
            int gr = row0 + ty * 8 + i;
            if (gr < M) {
                as_o[gr * heads + h] = ss;
                ad_o[gr * heads + h] = sd;
            }
        }
    }
}

// ---------------------------------------------------------------------------
// CSR build
// ---------------------------------------------------------------------------
__global__ void zero_cnt(int N)
{
    int i = blockIdx.x * blockDim.x + threadIdx.x;
    if (i < N) g_cnt[i] = 0;
}

__global__ void hist_k(const int* __restrict__ ei, int E, int Etot)
{
    int e = blockIdx.x * blockDim.x + threadIdx.x;
    if (e >= Etot) return;
    int d = (e < E) ? ei[E + e] : (e - E);
    atomicAdd(&g_cnt[d], 1);
}

__global__ void scan_k(int N, int Etot)
{
    __shared__ int wsum[32];
    int tid = threadIdx.x;
    const int PER = 12;
    int base = tid * PER;
    int loc[PER];
    int s = 0;
    #pragma unroll
    for (int i = 0; i < PER; i++) {
        int idx = base + i;
        int v = (idx < N) ? g_cnt[idx] : 0;
        loc[i] = s; s += v;
    }
    int lane = tid & 31, wid = tid >> 5;
    int x = s;
    #pragma unroll
    for (int o = 1; o < 32; o <<= 1) {
        int y = __shfl_up_sync(0xffffffffu, x, o);
        if (lane >= o) x += y;
    }
    if (lane == 31) wsum[wid] = x;
    __syncthreads();
    if (wid == 0) {
        int w = wsum[lane];
        #pragma unroll
        for (int o = 1; o < 32; o <<= 1) {
            int y = __shfl_up_sync(0xffffffffu, w, o);
            if (lane >= o) w += y;
        }
        wsum[lane] = w;
    }
    __syncthreads();
    int excl = x - s + (wid ? wsum[wid - 1] : 0);
    #pragma unroll
    for (int i = 0; i < PER; i++) {
        int idx = base + i;
        if (idx < N) { int v = excl + loc[i]; g_off[idx] = v; g_wp[idx] = v; }
    }
    if (tid == 0) g_off[N] = Etot;
}

__global__ void scatter_k(const int* __restrict__ ei, int E, int Etot)
{
    int e = blockIdx.x * blockDim.x + threadIdx.x;
    if (e >= Etot) return;
    int sIdx, d;
    if (e < E) { sIdx = ei[e]; d = ei[E + e]; } else { sIdx = d = e - E; }
    int pos = atomicAdd(&g_wp[d], 1);
    g_csr_src[pos] = sIdx;
}

// ---------------------------------------------------------------------------
// Single-pass aggregation, heads=4 (256 ch). One block per node (n0 offset).
// ---------------------------------------------------------------------------
__global__ void __launch_bounds__(128) agg4(
    const float* __restrict__ H, const float* __restrict__ as,
    const float* __restrict__ ad, const float* __restrict__ bias,
    const float* __restrict__ gam, const float* __restrict__ bet,
    const float* __restrict__ mu, const float* __restrict__ var,
    float* __restrict__ out, int n0)
{
    int n = n0 + blockIdx.x;
    int tid = threadIdx.x;
    int beg = g_off[n];
    int deg = g_off[n + 1] - beg;
    __shared__ float w_sh[256];
    __shared__ int   src_sh[64];
    __shared__ float red[128];
    __shared__ float inv_s[4];

    int ch = tid >> 2;
    int hh = tid & 3;
    int my_h = tid >> 5;
    int c = tid * 2;
    float adv = ad[n * 4 + hh];

    float a0x = 0.f, a0y = 0.f, a1x = 0.f, a1y = 0.f;
    float wsum = 0.f;

    for (int b0 = 0; b0 < deg; b0 += 64) {
        __syncthreads();
        #pragma unroll
        for (int q = 0; q < 2; q++) {
            int slot = ch + q * 32;
            int i = b0 + slot;
            if (i < deg) {
                int s = g_csr_src[beg + i];
                float l = as[s * 4 + hh] + adv;
                l = (l > 0.f) ? l : 0.2f * l;
                float w = __expf(l);
                w_sh[slot * 4 + hh] = w;
                wsum += w;
                if (hh == 0) src_sh[slot] = s;
            }
        }
        __syncthreads();
        int lim = min(64, deg - b0);
        int j = 0;
        for (; j + 2 <= lim; j += 2) {
            int s0 = src_sh[j];
            int s1 = src_sh[j + 1];
            float w0 = w_sh[j * 4 + my_h];
            float w1 = w_sh[(j + 1) * 4 + my_h];
            float2 h0 = __ldg(reinterpret_cast<const float2*>(H + (size_t)s0 * 256 + c));
            float2 h1 = __ldg(reinterpret_cast<const float2*>(H + (size_t)s1 * 256 + c));
            a0x += w0 * h0.x;  a0y += w0 * h0.y;
            a1x += w1 * h1.x;  a1y += w1 * h1.y;
        }
        if (j < lim) {
            int s0 = src_sh[j];
            float w0 = w_sh[j * 4 + my_h];
            float2 h0 = __ldg(reinterpret_cast<const float2*>(H + (size_t)s0 * 256 + c));
            a0x += w0 * h0.x;  a0y += w0 * h0.y;
        }
    }
    float accx = a0x + a1x;
    float accy = a0y + a1y;

    red[tid] = wsum; __syncthreads();
    #pragma unroll
    for (int s = 64; s >= 4; s >>= 1) {
        if (tid < s) red[tid] += red[tid + s];
        __syncthreads();
    }
    if (tid < 4) inv_s[tid] = 1.f / (red[tid] + 1e-16f);
    __syncthreads();
    float iv = inv_s[my_h];

    float v0 = accx * iv + bias[c];
    float v1 = accy * iv + bias[c + 1];
    v0 = (v0 > 0.f) ? v0 : (__expf(v0) - 1.f);
    v1 = (v1 > 0.f) ? v1 : (__expf(v1) - 1.f);
    float sc0 = gam[c]     * rsqrtf(var[c]     + 1e-5f);
    float sc1 = gam[c + 1] * rsqrtf(var[c + 1] + 1e-5f);
    v0 = sc0 * (v0 - mu[c])     + bet[c];
    v1 = sc1 * (v1 - mu[c + 1]) + bet[c + 1];
    out[(size_t)n * 256 + c]     = v0;
    out[(size_t)n * 256 + c + 1] = v1;
}

// ---------------------------------------------------------------------------
// Final layer aggregation + log_softmax. 64 threads per node (n0 offset).
// ---------------------------------------------------------------------------
__global__ void __launch_bounds__(64) agg_fin(
    const float* __restrict__ H, const float* __restrict__ as,
    const float* __restrict__ ad, const float* __restrict__ bias,
    float* __restrict__ out, int n0)
{
    int n = n0 + blockIdx.x, tid = threadIdx.x;
    int beg = g_off[n];
    int deg = g_off[n + 1] - beg;
    __shared__ float red[64];
    __shared__ float w_sh[64];
    __shared__ int   src_sh[64];
    float adv = ad[n];

    float acc0 = 0.f, acc1 = 0.f, wsum = 0.f;
    for (int b0 = 0; b0 < deg; b0 += 64) {
        int i = b0 + tid;
        __syncthreads();
        if (i < deg) {
            int s = g_csr_src[beg + i];
            float l = as[s] + adv; l = (l > 0.f) ? l : 0.2f * l;
            float w = __expf(l);
            w_sh[tid] = w;
            src_sh[tid] = s;
            wsum += w;
        }
        __syncthreads();
        int lim = min(64, deg - b0);
        int j = 0;
        for (; j + 2 <= lim; j += 2) {
            acc0 += w_sh[j]     * __ldg(H + (size_t)src_sh[j]     * 64 + tid);
            acc1 += w_sh[j + 1] * __ldg(H + (size_t)src_sh[j + 1] * 64 + tid);
        }
        if (j < lim)
            acc0 += w_sh[j] * __ldg(H + (size_t)src_sh[j] * 64 + tid);
    }
    float acc = acc0 + acc1;

    red[tid] = wsum; __syncthreads();
    #pragma unroll
    for (int s = 32; s >= 1; s >>= 1) {
        if (tid < s) red[tid] += red[tid + s];
        __syncthreads();
    }
    float iv = 1.f / (red[0] + 1e-16f);
    __syncthreads();

    float z = acc * iv + bias[tid];

    red[tid] = z; __syncthreads();
    #pragma unroll
    for (int s = 32; s >= 1; s >>= 1) {
        if (tid < s) red[tid] = fmaxf(red[tid], red[tid + s]);
        __syncthreads();
    }
    float zm = red[0]; __syncthreads();
    red[tid] = __expf(z - zm); __syncthreads();
    #pragma unroll
    for (int s = 32; s >= 1; s >>= 1) {
        if (tid < s) red[tid] += red[tid + s];
        __syncthreads();
    }
    float lse = zm + logf(red[0]);
    out[(size_t)n * 64 + tid] = z - lse;
}

// ---------------------------------------------------------------------------
extern "C" void kernel_launch(void* const* d_in, const int* in_sizes, int n_in,
                              void* d_out, int out_size)
{
    const float* x    = (const float*)d_in[0];
    const int*   ei   = (const int*)  d_in[1];
    const float* W0   = (const float*)d_in[2];
    const float* as0w = (const float*)d_in[3];
    const float* ad0w = (const float*)d_in[4];
    const float* b0   = (const float*)d_in[5];
    const float* gm0  = (const float*)d_in[6];
    const float* be0  = (const float*)d_in[7];
    const float* mu0  = (const float*)d_in[8];
    const float* vr0  = (const float*)d_in[9];
    const float* W1   = (const float*)d_in[10];
    const float* as1w = (const float*)d_in[11];
    const float* ad1w = (const float*)d_in[12];
    const float* b1   = (const float*)d_in[13];
    const float* gm1  = (const float*)d_in[14];
    const float* be1  = (const float*)d_in[15];
    const float* mu1  = (const float*)d_in[16];
    const float* vr1  = (const float*)d_in[17];
    const float* W2   = (const float*)d_in[18];
    const float* as2w = (const float*)d_in[19];
    const float* ad2w = (const float*)d_in[20];
    const float* b2   = (const float*)d_in[21];

    int N = in_sizes[0] / 128;      // 10000
    int E = in_sizes[1] / 2;        // 320000
    int Etot = E + N;

    float *H0, *H1, *X, *AS0, *AS1, *AD0, *AD1;
    cudaGetSymbolAddress((void**)&H0, g_H);
    H1 = H0 + (size_t)MAXN * 256;
    cudaGetSymbolAddress((void**)&X,  g_X);
    cudaGetSymbolAddress((void**)&AS0, g_as);
    AS1 = AS0 + MAXN * 4;
    cudaGetSymbolAddress((void**)&AD0, g_ad);
    AD1 = AD0 + MAXN * 4;

    static cudaStream_t s2 = nullptr;
    static cudaEvent_t evFork = nullptr, evCSR, evA0a, evG1a, evG1b, evA1a,
                       evG2a, evG2b, evEnd;
    if (!s2) {
        cudaStreamCreateWithFlags(&s2, cudaStreamNonBlocking);
        cudaEventCreateWithFlags(&evFork, cudaEventDisableTiming);
        cudaEventCreateWithFlags(&evCSR,  cudaEventDisableTiming);
        cudaEventCreateWithFlags(&evA0a,  cudaEventDisableTiming);
        cudaEventCreateWithFlags(&evG1a,  cudaEventDisableTiming);
        cudaEventCreateWithFlags(&evG1b,  cudaEventDisableTiming);
        cudaEventCreateWithFlags(&evA1a,  cudaEventDisableTiming);
        cudaEventCreateWithFlags(&evG2a,  cudaEventDisableTiming);
        cudaEventCreateWithFlags(&evG2b,  cudaEventDisableTiming);
        cudaEventCreateWithFlags(&evEnd,  cudaEventDisableTiming);
    }

    const int NH = 5056;            // 79 * 64 — exact GEMM-tile boundary
    int NB = N - NH;                // 4944
    int gax = NH / 64;              // 79
    int gbx = (NB + 63) / 64;       // 78
    int gfull = (N + 63) / 64;      // 157

    // ---- fork: CSR on s2 ----
    cudaEventRecord(evFork, 0);
    cudaStreamWaitEvent(s2, evFork, 0);
    zero_cnt<<<(N + 255) / 256, 256, 0, s2>>>(N);
    hist_k<<<(Etot + 255) / 256, 256, 0, s2>>>(ei, E, Etot);
    scan_k<<<1, 1024, 0, s2>>>(N, Etot);
    scatter_k<<<(Etot + 255) / 256, 256, 0, s2>>>(ei, E, Etot);
    cudaEventRecord(evCSR, s2);

    // ---- layer 0: full GEMM on main (overlaps CSR) ----
    gemm64att<<<dim3(gfull, 4), 128>>>(x, W0, H0, as0w, ad0w, AS0, AD0,
                                       N, 256, 128, 4, 0);
    cudaStreamWaitEvent(0, evCSR, 0);
    agg4<<<NH, 128>>>(H0, AS0, AD0, b0, gm0, be0, mu0, vr0, X, 0);
    cudaEventRecord(evA0a, 0);

    // s2: A0b staggered after A0a (overlaps G1a below)
    cudaStreamWaitEvent(s2, evA0a, 0);
    agg4<<<NB, 128, 0, s2>>>(H0, AS0, AD0, b0, gm0, be0, mu0, vr0, X, NH);

    // main: G1a (rows [0,NH)) — concurrent with A0b
    gemm64att<<<dim3(gax, 4), 128>>>(X, W1, H1, as1w, ad1w, AS1, AD1,
                                     N, 256, 256, 4, 0);
    cudaEventRecord(evG1a, 0);

    // s2: G1b after A0b
    gemm64att<<<dim3(gbx, 4), 128, 0, s2>>>(X, W1, H1, as1w, ad1w, AS1, AD1,
                                            N, 256, 256, 4, NH);
    cudaEventRecord(evG1b, s2);

    // main: A1a needs full H1
    cudaStreamWaitEvent(0, evG1b, 0);
    agg4<<<NH, 128>>>(H1, AS1, AD1, b1, gm1, be1, mu1, vr1, X, 0);
    cudaEventRecord(evA1a, 0);

    // s2: A1b staggered (needs G1a + in-stream G1b) — overlaps G2a
    cudaStreamWaitEvent(s2, evG1a, 0);
    cudaStreamWaitEvent(s2, evA1a, 0);
    agg4<<<NB, 128, 0, s2>>>(H1, AS1, AD1, b1, gm1, be1, mu1, vr1, X, NH);

    // main: G2a — concurrent with A1b
    gemm64att<<<dim3(gax, 1), 128>>>(X, W2, H0, as2w, ad2w, AS0, AD0,
                                     N, 64, 256, 1, 0);
    cudaEventRecord(evG2a, 0);

    // s2: G2b after A1b
    gemm64att<<<dim3(gbx, 1), 128, 0, s2>>>(X, W2, H0, as2w, ad2w, AS0, AD0,
                                            N, 64, 256, 1, NH);
    cudaEventRecord(evG2b, s2);

    // main: FINa needs full layer-2 H/as/ad
    cudaStreamWaitEvent(0, evG2b, 0);
    agg_fin<<<NH, 64>>>(H0, AS0, AD0, b2, (float*)d_out, 0);

    // s2: FINb
    cudaStreamWaitEvent(s2, evG2a, 0);
    agg_fin<<<NB, 64, 0, s2>>>(H0, AS0, AD0, b2, (float*)d_out, NH);
    cudaEventRecord(evEnd, s2);

    // join
    cudaStreamWaitEvent(0, evEnd, 0);
}

// round 10
// speedup vs baseline: 1.0537x; 1.0537x over previous
#include <cuda_runtime.h>
#include <cuda_bf16.h>
#include <cstdint>

// ---------------------------------------------------------------------------
// GAT 3-layer forward. GEMMs on tensor pipe via portable mma.sync
// (m16n8k16 bf16, fp32 accum) with bf16x2 hi/lo split (3 products) for
// fp32-grade accuracy. CSR build forked on a side stream under GEMM0.
// Aggregation: single-pass softmax-gather (unchanged, L2-bound).
// ---------------------------------------------------------------------------

#define MAXN 10240
#define MAXE 340000

__device__ float g_H[MAXN * 256];
__device__ float g_X[MAXN * 256];
__device__ float g_as[MAXN * 4];
__device__ float g_ad[MAXN * 4];
__device__ int   g_cnt[MAXN];
__device__ int   g_off[MAXN + 1];
__device__ int   g_wp[MAXN];
__device__ int   g_csr_src[MAXE];
// bf16 hi/lo split, transposed weights, [n][k] layout:
// L0 hi @0 (32768), L0 lo @32768, L1 hi @65536, L1 lo @131072,
// L2 hi @196608, L2 lo @212992   (elements, bf16)
__device__ __nv_bfloat16 g_wtb[229376];

// ---------------------------------------------------------------------------
// Weight prep: W [K][NF] fp32 row-major -> hi/lo bf16 [NF][K].
// ---------------------------------------------------------------------------
__global__ void wt_prep(const float* __restrict__ W, __nv_bfloat16* __restrict__ hi,
                        __nv_bfloat16* __restrict__ lo, int K, int NF)
{
    int e = blockIdx.x * blockDim.x + threadIdx.x;
    if (e >= K * NF) return;
    int k = e / NF, n = e - k * NF;
    float v = W[e];
    __nv_bfloat16 h = __float2bfloat16_rn(v);
    float r = v - __bfloat162float(h);
    hi[(size_t)n * K + k] = h;
    lo[(size_t)n * K + k] = __float2bfloat16_rn(r);
}

// ---------------------------------------------------------------------------
// mma.sync GEMM: C[M,NF] = A[M,K] @ W. Block tile 64 rows x 64 cols,
// 128 threads (4 warps x 16 rows x 64 cols). K-step 16.
// SMEM tiles stored in fragment order: A [mb][lane][reg0..3] (u32 = bf16x2),
// B [nf][lane][reg0..1]. Fused attention-dot epilogue (tile cols == head).
// ---------------------------------------------------------------------------
__device__ __forceinline__ uint32_t pack_bf2(float e0, float e1)
{
    __nv_bfloat162 p = __floats2bfloat162_rn(e0, e1);   // e0 -> low 16 bits
    return *reinterpret_cast<uint32_t*>(&p);
}

__device__ __forceinline__ void mma_bf16(float c[4], const uint32_t a[4],
                                         uint32_t b0, uint32_t b1)
{
    asm volatile(
        "mma.sync.aligned.m16n8k16.row.col.f32.bf16.bf16.f32 "
        "{%0,%1,%2,%3}, {%4,%5,%6,%7}, {%8,%9}, {%0,%1,%2,%3};"
        : "+f"(c[0]), "+f"(c[1]), "+f"(c[2]), "+f"(c[3])
        : "r"(a[0]), "r"(a[1]), "r"(a[2]), "r"(a[3]), "r"(b0), "r"(b1));
}

__global__ void __launch_bounds__(128) gemm_mma(
    const float* __restrict__ A,
    const __nv_bfloat16* __restrict__ Bhi, const __nv_bfloat16* __restrict__ Blo,
    float* __restrict__ C,
    const float* __restrict__ asw, const float* __restrict__ adw,
    float* __restrict__ as_o, float* __restrict__ ad_o,
    int M, int NF, int K, int heads)
{
    __shared__ uint32_t Ah[4][32][4];
    __shared__ uint32_t Al[4][32][4];
    __shared__ uint32_t Bh[8][32][2];
    __shared__ uint32_t Bl[8][32][2];

    int tid = threadIdx.x;
    int warp = tid >> 5, lane = tid & 31;
    int m0 = blockIdx.x * 64, n0 = blockIdx.y * 64;

    float c[8][4];
    #pragma unroll
    for (int f = 0; f < 8; f++)
        #pragma unroll
        for (int q = 0; q < 4; q++) c[f][q] = 0.f;

    for (int k0 = 0; k0 < K; k0 += 16) {
        // ---- stage A (64x16 fp32 -> hi/lo bf16x2 fragments) ----
        #pragma unroll
        for (int i = 0; i < 2; i++) {
            int e = tid * 2 + i;            // 0..255 float4 slots
            int row = e >> 2, kq = (e & 3) * 4;
            int gr = m0 + row;
            float4 v = make_float4(0.f, 0.f, 0.f, 0.f);
            if (gr < M) v = *reinterpret_cast<const float4*>(A + (size_t)gr * K + k0 + kq);
            int mb = row >> 4;
            int rbase = ((row & 15) >= 8) ? 1 : 0;
            int t = (row & 7) * 4;
            #pragma unroll
            for (int p = 0; p < 2; p++) {
                float f0 = p ? v.z : v.x;
                float f1 = p ? v.w : v.y;
                int cp = (kq >> 1) + p;     // k-pair index 0..7
                __nv_bfloat16 h0 = __float2bfloat16_rn(f0);
                __nv_bfloat16 h1 = __float2bfloat16_rn(f1);
                float l0 = f0 - __bfloat162float(h0);
                float l1 = f1 - __bfloat162float(h1);
                __nv_bfloat162 hp2 = __nv_bfloat162(h0, h1);
                uint32_t hp = *reinterpret_cast<uint32_t*>(&hp2);
                uint32_t lp = pack_bf2(l0, l1);
                int r = rbase + ((cp >= 4) ? 2 : 0);
                int tt = t + (cp & 3);
                Ah[mb][tt][r] = hp;
                Al[mb][tt][r] = lp;
            }
        }
        // ---- stage B (64n x 8 k-pairs, pre-split bf16 [n][k]) ----
        #pragma unroll
        for (int i = 0; i < 4; i++) {
            int e = tid + i * 128;          // 0..511
            int n = e >> 3, cp = e & 7;
            uint32_t hp = *reinterpret_cast<const uint32_t*>(
                Bhi + (size_t)(n0 + n) * K + k0 + cp * 2);
            uint32_t lp = *reinterpret_cast<const uint32_t*>(
                Blo + (size_t)(n0 + n) * K + k0 + cp * 2);
            int nf = n >> 3, r = cp >> 2, tt = (n & 7) * 4 + (cp & 3);
            Bh[nf][tt][r] = hp;
            Bl[nf][tt][r] = lp;
        }
        __syncthreads();

        // ---- compute ----
        uint4 ah4 = *reinterpret_cast<const uint4*>(&Ah[warp][lane][0]);
        uint4 al4 = *reinterpret_cast<const uint4*>(&Al[warp][lane][0]);
        uint32_t ah[4] = {ah4.x, ah4.y, ah4.z, ah4.w};
        uint32_t al[4] = {al4.x, al4.y, al4.z, al4.w};
        #pragma unroll
        for (int nf = 0; nf < 8; nf++) {
            uint2 bh = *reinterpret_cast<const uint2*>(&Bh[nf][lane][0]);
            uint2 bl = *reinterpret_cast<const uint2*>(&Bl[nf][lane][0]);
            mma_bf16(c[nf], ah, bh.x, bh.y);
            mma_bf16(c[nf], ah, bl.x, bl.y);
            mma_bf16(c[nf], al, bh.x, bh.y);
        }
        __syncthreads();
    }

    // ---- epilogue: store C + fused attention dots ----
    int r0 = m0 + warp * 16 + (lane >> 2);
    int r1 = r0 + 8;
    int cb = (lane & 3) * 2;

    float ss0 = 0.f, sd0 = 0.f, ss1 = 0.f, sd1 = 0.f;
    #pragma unroll
    for (int nf = 0; nf < 8; nf++) {
        int col = n0 + nf * 8 + cb;
        float w0 = asw[col], w1 = asw[col + 1];
        float d0 = adw[col], d1 = adw[col + 1];
        ss0 += c[nf][0] * w0 + c[nf][1] * w1;
        sd0 += c[nf][0] * d0 + c[nf][1] * d1;
        ss1 += c[nf][2] * w0 + c[nf][3] * w1;
        sd1 += c[nf][2] * d0 + c[nf][3] * d1;
        if (r0 < M) {
            float2 v = make_float2(c[nf][0], c[nf][1]);
            *reinterpret_cast<float2*>(C + (size_t)r0 * NF + col) = v;
        }
        if (r1 < M) {
            float2 v = make_float2(c[nf][2], c[nf][3]);
            *reinterpret_cast<float2*>(C + (size_t)r1 * NF + col) = v;
        }
    }
    // reduce over the 4 lanes sharing a row (lane bits 0-1)
    #pragma unroll
    for (int o = 1; o <= 2; o <<= 1) {
        ss0 += __shfl_xor_sync(0xffffffffu, ss0, o);
        sd0 += __shfl_xor_sync(0xffffffffu, sd0, o);
        ss1 += __shfl_xor_sync(0xffffffffu, ss1, o);
        sd1 += __shfl_xor_sync(0xffffffffu, sd1, o);
    }
    int h = blockIdx.y;
    if ((lane & 3) == 0) {
        if (r0 < M) { as_o[r0 * heads + h] = ss0; ad_o[r0 * heads + h] = sd0; }
        if (r1 < M) { as_o[r1 * heads + h] = ss1; ad_o[r1 * heads + h] = sd1; }
    }
}

// ---------------------------------------------------------------------------
// CSR build
// ---------------------------------------------------------------------------
__global__ void zero_cnt(int N)
{
    int i = blockIdx.x * blockDim.x + threadIdx.x;
    if (i < N) g_cnt[i] = 0;
}

__global__ void hist_k(const int* __restrict__ ei, int E, int Etot)
{
    int e = blockIdx.x * blockDim.x + threadIdx.x;
    if (e >= Etot) return;
    int d = (e < E) ? ei[E + e] : (e - E);
    atomicAdd(&g_cnt[d], 1);
}

__global__ void scan_k(int N, int Etot)
{
    __shared__ int wsum[32];
    int tid = threadIdx.x;
    const int PER = 12;
    int base = tid * PER;
    int loc[PER];
    int s = 0;
    #pragma unroll
    for (int i = 0; i < PER; i++) {
        int idx = base + i;
        int v = (idx < N) ? g_cnt[idx] : 0;
        loc[i] = s; s += v;
    }
    int lane = tid & 31, wid = tid >> 5;
    int x = s;
    #pragma unroll
    for (int o = 1; o < 32; o <<= 1) {
        int y = __shfl_up_sync(0xffffffffu, x, o);
        if (lane >= o) x += y;
    }
    if (lane == 31) wsum[wid] = x;
    __syncthreads();
    if (wid == 0) {
        int w = wsum[lane];
        #pragma unroll
        for (int o = 1; o < 32; o <<= 1) {
            int y = __shfl_up_sync(0xffffffffu, w, o);
            if (lane >= o) w += y;
        }
        wsum[lane] = w;
    }
    __syncthreads();
    int excl = x - s + (wid ? wsum[wid - 1] : 0);
    #pragma unroll
    for (int i = 0; i < PER; i++) {
        int idx = base + i;
        if (idx < N) { int v = excl + loc[i]; g_off[idx] = v; g_wp[idx] = v; }
    }
    if (tid == 0) g_off[N] = Etot;
}

__global__ void scatter_k(const int* __restrict__ ei, int E, int Etot)
{
    int e = blockIdx.x * blockDim.x + threadIdx.x;
    if (e >= Etot) return;
    int sIdx, d;
    if (e < E) { sIdx = ei[e]; d = ei[E + e]; } else { sIdx = d = e - E; }
    int pos = atomicAdd(&g_wp[d], 1);
    g_csr_src[pos] = sIdx;
}

// ---------------------------------------------------------------------------
// Single-pass aggregation, heads=4 (256 ch). One block/node, 128 threads.
// ---------------------------------------------------------------------------
__global__ void __launch_bounds__(128) agg4(
    const float* __restrict__ H, const float* __restrict__ as,
    const float* __restrict__ ad, const float* __restrict__ bias,
    const float* __restrict__ gam, const float* __restrict__ bet,
    const float* __restrict__ mu, const float* __restrict__ var,
    float* __restrict__ out)
{
    int n = blockIdx.x;
    int tid = threadIdx.x;
    int beg = g_off[n];
    int deg = g_off[n + 1] - beg;
    __shared__ float w_sh[256];
    __shared__ int   src_sh[64];
    __shared__ float red[128];
    __shared__ float inv_s[4];

    int ch = tid >> 2;
    int hh = tid & 3;
    int my_h = tid >> 5;
    int c = tid * 2;
    float adv = ad[n * 4 + hh];

    float a0x = 0.f, a0y = 0.f, a1x = 0.f, a1y = 0.f;
    float wsum = 0.f;

    for (int b0 = 0; b0 < deg; b0 += 64) {
        __syncthreads();
        #pragma unroll
        for (int q = 0; q < 2; q++) {
            int slot = ch + q * 32;
            int i = b0 + slot;
            if (i < deg) {
                int s = g_csr_src[beg + i];
                float l = as[s * 4 + hh] + adv;
                l = (l > 0.f) ? l : 0.2f * l;
                float w = __expf(l);
                w_sh[slot * 4 + hh] = w;
                wsum += w;
                if (hh == 0) src_sh[slot] = s;
            }
        }
        __syncthreads();
        int lim = min(64, deg - b0);
        int j = 0;
        for (; j + 2 <= lim; j += 2) {
            int s0 = src_sh[j];
            int s1 = src_sh[j + 1];
            float w0 = w_sh[j * 4 + my_h];
            float w1 = w_sh[(j + 1) * 4 + my_h];
            float2 h0 = __ldg(reinterpret_cast<const float2*>(H + (size_t)s0 * 256 + c));
            float2 h1 = __ldg(reinterpret_cast<const float2*>(H + (size_t)s1 * 256 + c));
            a0x += w0 * h0.x;  a0y += w0 * h0.y;
            a1x += w1 * h1.x;  a1y += w1 * h1.y;
        }
        if (j < lim) {
            int s0 = src_sh[j];
            float w0 = w_sh[j * 4 + my_h];
            float2 h0 = __ldg(reinterpret_cast<const float2*>(H + (size_t)s0 * 256 + c));
            a0x += w0 * h0.x;  a0y += w0 * h0.y;
        }
    }
    float accx = a0x + a1x;
    float accy = a0y + a1y;

    red[tid] = wsum; __syncthreads();
    #pragma unroll
    for (int s = 64; s >= 4; s >>= 1) {
        if (tid < s) red[tid] += red[tid + s];
        __syncthreads();
    }
    if (tid < 4) inv_s[tid] = 1.f / (red[tid] + 1e-16f);
    __syncthreads();
    float iv = inv_s[my_h];

    float v0 = accx * iv + bias[c];
    float v1 = accy * iv + bias[c + 1];
    v0 = (v0 > 0.f) ? v0 : (__expf(v0) - 1.f);
    v1 = (v1 > 0.f) ? v1 : (__expf(v1) - 1.f);
    float sc0 = gam[c]     * rsqrtf(var[c]     + 1e-5f);
    float sc1 = gam[c + 1] * rsqrtf(var[c + 1] + 1e-5f);
    v0 = sc0 * (v0 - mu[c])     + bet[c];
    v1 = sc1 * (v1 - mu[c + 1]) + bet[c + 1];
    out[(size_t)n * 256 + c]     = v0;
    out[(size_t)n * 256 + c + 1] = v1;
}

// ---------------------------------------------------------------------------
// Final layer aggregation + log_softmax. 64 threads/node.
// ---------------------------------------------------------------------------
__global__ void __launch_bounds__(64) agg_fin(
    const float* __restrict__ H, const float* __restrict__ as,
    const float* __restrict__ ad, const float* __restrict__ bias,
    float* __restrict__ out)
{
    int n = blockIdx.x, tid = threadIdx.x;
    int beg = g_off[n];
    int deg = g_off[n + 1] - beg;
    __shared__ float red[64];
    __shared__ float w_sh[64];
    __shared__ int   src_sh[64];
    float adv = ad[n];

    float acc0 = 0.f, acc1 = 0.f, wsum = 0.f;
    for (int b0 = 0; b0 < deg; b0 += 64) {
        int i = b0 + tid;
        __syncthreads();
        if (i < deg) {
            int s = g_csr_src[beg + i];
            float l = as[s] + adv; l = (l > 0.f) ? l : 0.2f * l;
            float w = __expf(l);
            w_sh[tid] = w;
            src_sh[tid] = s;
            wsum += w;
        }
        __syncthreads();
        int lim = min(64, deg - b0);
        int j = 0;
        for (; j + 2 <= lim; j += 2) {
            acc0 += w_sh[j]     * __ldg(H + (size_t)src_sh[j]     * 64 + tid);
            acc1 += w_sh[j + 1] * __ldg(H + (size_t)src_sh[j + 1] * 64 + tid);
        }
        if (j < lim)
            acc0 += w_sh[j] * __ldg(H + (size_t)src_sh[j] * 64 + tid);
    }
    float acc = acc0 + acc1;

    red[tid] = wsum; __syncthreads();
    #pragma unroll
    for (int s = 32; s >= 1; s >>= 1) {
        if (tid < s) red[tid] += red[tid + s];
        __syncthreads();
    }
    float iv = 1.f / (red[0] + 1e-16f);
    __syncthreads();

    float z = acc * iv + bias[tid];

    red[tid] = z; __syncthreads();
    #pragma unroll
    for (int s = 32; s >= 1; s >>= 1) {
        if (tid < s) red[tid] = fmaxf(red[tid], red[tid + s]);
        __syncthreads();
    }
    float zm = red[0]; __syncthreads();
    red[tid] = __expf(z - zm); __syncthreads();
    #pragma unroll
    for (int s = 32; s >= 1; s >>= 1) {
        if (tid < s) red[tid] += red[tid + s];
        __syncthreads();
    }
    float lse = zm + logf(red[0]);
    out[(size_t)n * 64 + tid] = z - lse;
}

// ---------------------------------------------------------------------------
extern "C" void kernel_launch(void* const* d_in, const int* in_sizes, int n_in,
                              void* d_out, int out_size)
{
    const float* x    = (const float*)d_in[0];
    const int*   ei   = (const int*)  d_in[1];
    const float* W0   = (const float*)d_in[2];
    const float* as0w = (const float*)d_in[3];
    const float* ad0w = (const float*)d_in[4];
    const float* b0   = (const float*)d_in[5];
    const float* gm0  = (const float*)d_in[6];
    const float* be0  = (const float*)d_in[7];
    const float* mu0  = (const float*)d_in[8];
    const float* vr0  = (const float*)d_in[9];
    const float* W1   = (const float*)d_in[10];
    const float* as1w = (const float*)d_in[11];
    const float* ad1w = (const float*)d_in[12];
    const float* b1   = (const float*)d_in[13];
    const float* gm1  = (const float*)d_in[14];
    const float* be1  = (const float*)d_in[15];
    const float* mu1  = (const float*)d_in[16];
    const float* vr1  = (const float*)d_in[17];
    const float* W2   = (const float*)d_in[18];
    const float* as2w = (const float*)d_in[19];
    const float* ad2w = (const float*)d_in[20];
    const float* b2   = (const float*)d_in[21];

    int N = in_sizes[0] / 128;      // 10000
    int E = in_sizes[1] / 2;        // 320000
    int Etot = E + N;

    float *H, *X, *AS, *AD;
    __nv_bfloat16* WTB;
    cudaGetSymbolAddress((void**)&H,  g_H);
    cudaGetSymbolAddress((void**)&X,  g_X);
    cudaGetSymbolAddress((void**)&AS, g_as);
    cudaGetSymbolAddress((void**)&AD, g_ad);
    cudaGetSymbolAddress((void**)&WTB, g_wtb);
    __nv_bfloat16* w0h = WTB;            __nv_bfloat16* w0l = WTB + 32768;
    __nv_bfloat16* w1h = WTB + 65536;    __nv_bfloat16* w1l = WTB + 131072;
    __nv_bfloat16* w2h = WTB + 196608;   __nv_bfloat16* w2l = WTB + 212992;

    static cudaStream_t s2 = nullptr;
    static cudaEvent_t evFork = nullptr, evJoin = nullptr;
    if (!s2) {
        cudaStreamCreateWithFlags(&s2, cudaStreamNonBlocking);
        cudaEventCreateWithFlags(&evFork, cudaEventDisableTiming);
        cudaEventCreateWithFlags(&evJoin, cudaEventDisableTiming);
    }

    // fork: CSR build on s2
    cudaEventRecord(evFork, 0);
    cudaStreamWaitEvent(s2, evFork, 0);
    zero_cnt<<<(N + 255) / 256, 256, 0, s2>>>(N);
    hist_k<<<(Etot + 255) / 256, 256, 0, s2>>>(ei, E, Etot);
    scan_k<<<1, 1024, 0, s2>>>(N, Etot);
    scatter_k<<<(Etot + 255) / 256, 256, 0, s2>>>(ei, E, Etot);
    cudaEventRecord(evJoin, s2);

    int gx = (N + 63) / 64;         // 157

    // weight prep + layer 0 (all on main, overlapping CSR build)
    wt_prep<<<(128 * 256 + 255) / 256, 256>>>(W0, w0h, w0l, 128, 256);
    gemm_mma<<<dim3(gx, 4), 128>>>(x, w0h, w0l, H, as0w, ad0w, AS, AD, N, 256, 128, 4);
    wt_prep<<<(256 * 256 + 255) / 256, 256>>>(W1, w1h, w1l, 256, 256);
    wt_prep<<<(256 * 64  + 255) / 256, 256>>>(W2, w2h, w2l, 256, 64);
    cudaStreamWaitEvent(0, evJoin, 0);
    agg4<<<N, 128>>>(H, AS, AD, b0, gm0, be0, mu0, vr0, X);

    // layer 1
    gemm_mma<<<dim3(gx, 4), 128>>>(X, w1h, w1l, H, as1w, ad1w, AS, AD, N, 256, 256, 4);
    agg4<<<N, 128>>>(H, AS, AD, b1, gm1, be1, mu1, vr1, X);

    // layer 2 + log_softmax
    gemm_mma<<<dim3(gx, 1), 128>>>(X, w2h, w2l, H, as2w, ad2w, AS, AD, N, 64, 256, 1);
    agg_fin<<<N, 64>>>(H, AS, AD, b2, (float*)d_out);
}